// round 13
// baseline (speedup 1.0000x reference)
#include <cuda_runtime.h>
#include <cstdint>

// Scratch for the three bilinear outputs (with the appended ones column):
// g_o[m][b*64 + k], k in [0,63); column 63 == 1.0f.  3*512*64*4 = 384 KB.
__device__ __align__(16) float g_o[3][512 * 64];

// ---------- packed f32x2 helpers (Blackwell) ----------
__device__ __forceinline__ unsigned long long pk(float lo, float hi) {
    unsigned long long r;
    asm("mov.b64 %0, {%1, %2};" : "=l"(r) : "f"(lo), "f"(hi));
    return r;
}
__device__ __forceinline__ unsigned long long f2(unsigned long long a,
                                                 unsigned long long b,
                                                 unsigned long long c) {
    unsigned long long d;
    asm("fma.rn.f32x2 %0, %1, %2, %3;" : "=l"(d) : "l"(a), "l"(b), "l"(c));
    return d;
}
__device__ __forceinline__ void upk(unsigned long long v, float& lo, float& hi) {
    asm("mov.b64 {%0, %1}, %2;" : "=f"(lo), "=f"(hi) : "l"(v));
}

// ---------------------------------------------------------------------------
// Stage 1: o_m[b,k] = sum_ij A[b,i] * W[k,i,j] * C[b,j] + bias[k]
// grid = (63 k, 3 forms, 4 b-tiles), block = 128 threads (one b per thread).
// W[k] staged in smem (16 KB, broadcast reads). C row packed as 32 f32x2 regs
// (j-adjacent pairing -> W pairs come straight out of smem as ulonglong2,
// no repacking movs in the hot loop).  ~34 fma2 per 64 MACs => fma-pipe bound.
// ---------------------------------------------------------------------------
__global__ __launch_bounds__(128) void bilinear_k(
    const float* __restrict__ x, const float* __restrict__ y,
    const float* __restrict__ z,
    const float* __restrict__ W1, const float* __restrict__ b1,
    const float* __restrict__ W2, const float* __restrict__ b2,
    const float* __restrict__ W3, const float* __restrict__ b3) {
    __shared__ __align__(16) float Ws[64 * 64];

    const int k = blockIdx.x;
    const int m = blockIdx.y;
    const int b = blockIdx.z * 128 + threadIdx.x;

    const float* A;
    const float* C;
    const float* W;
    const float* bias;
    if (m == 0)      { A = x; C = y; W = W1; bias = b1; }
    else if (m == 1) { A = x; C = z; W = W2; bias = b2; }
    else             { A = y; C = z; W = W3; bias = b3; }

    // Cooperative load of W[k] (16 KB) into shared, float4-wide, coalesced.
    const float4* Wg = (const float4*)(W + (size_t)k * 4096);
    #pragma unroll
    for (int q = 0; q < 8; ++q)
        ((float4*)Ws)[threadIdx.x + 128 * q] = Wg[threadIdx.x + 128 * q];

    // Pack this thread's C row into 32 f32x2 registers (j-pairs).
    unsigned long long c2[32];
    const float4* c4 = (const float4*)(C + (size_t)b * 64);
    #pragma unroll
    for (int q = 0; q < 16; ++q) {
        float4 v = c4[q];
        c2[2 * q]     = pk(v.x, v.y);
        c2[2 * q + 1] = pk(v.z, v.w);
    }
    __syncthreads();

    unsigned long long accA = 0ull, accB = 0ull;  // bit pattern of {0.f,0.f}
    const float* Arow = A + (size_t)b * 64;

    #pragma unroll 2
    for (int i = 0; i < 64; ++i) {
        const ulonglong2* wr = (const ulonglong2*)(Ws + i * 64);
        unsigned long long sA = 0ull, sB = 0ull;  // 2 chains for ILP
        #pragma unroll
        for (int q = 0; q < 8; ++q) {
            ulonglong2 w0 = wr[2 * q];
            ulonglong2 w1 = wr[2 * q + 1];
            sA = f2(w0.x, c2[4 * q],     sA);
            sB = f2(w0.y, c2[4 * q + 1], sB);
            sA = f2(w1.x, c2[4 * q + 2], sA);
            sB = f2(w1.y, c2[4 * q + 3], sB);
        }
        float ai = __ldg(Arow + i);
        unsigned long long a2 = pk(ai, ai);
        accA = f2(a2, sA, accA);
        accB = f2(a2, sB, accB);
    }

    float la, ha, lb, hb;
    upk(accA, la, ha);
    upk(accB, lb, hb);
    float o = (la + ha) + (lb + hb) + __ldg(bias + k);

    g_o[m][b * 64 + k] = o;
    if (k == 0) g_o[m][b * 64 + 63] = 1.0f;  // appended ones column
}

// ---------------------------------------------------------------------------
// Stage 2: out[b, i*4096 + j*64 + k] = o1[b,i] * o2[b,j] * o3[b,k]
// grid = (64 i, 512 b), block = 256.  Each thread: kq = tid&15 is FIXED, so
// its o3 float4 lives in registers; 4 perfectly coalesced STG.128 per thread.
// Pure store-bandwidth kernel (~512 MB total).
// ---------------------------------------------------------------------------
__global__ __launch_bounds__(256) void outer_k(float* __restrict__ out) {
    const int i = blockIdx.x;
    const int b = blockIdx.y;
    const float* o1 = g_o[0] + b * 64;
    const float* o2 = g_o[1] + b * 64;
    const float* o3 = g_o[2] + b * 64;

    const float o1i = __ldg(o1 + i);
    const float4 w = ((const float4*)o3)[threadIdx.x & 15];

    float4* out4 = (float4*)out + (size_t)b * 65536 + (size_t)i * 1024;
    const int jb = threadIdx.x >> 4;

    #pragma unroll
    for (int u = 0; u < 4; ++u) {
        float v = o1i * __ldg(o2 + jb + 16 * u);
        float4 r;
        r.x = v * w.x;
        r.y = v * w.y;
        r.z = v * w.z;
        r.w = v * w.w;
        out4[threadIdx.x + 256 * u] = r;
    }
}

extern "C" void kernel_launch(void* const* d_in, const int* in_sizes, int n_in,
                              void* d_out, int out_size) {
    const float* x  = (const float*)d_in[0];
    const float* y  = (const float*)d_in[1];
    const float* z  = (const float*)d_in[2];
    const float* W1 = (const float*)d_in[3];
    const float* b1 = (const float*)d_in[4];
    const float* W2 = (const float*)d_in[5];
    const float* b2 = (const float*)d_in[6];
    const float* W3 = (const float*)d_in[7];
    const float* b3 = (const float*)d_in[8];
    float* out = (float*)d_out;

    dim3 g1(63, 3, 4);
    bilinear_k<<<g1, 128>>>(x, y, z, W1, b1, W2, b2, W3, b3);

    dim3 g2(64, 512);
    outer_k<<<g2, 256>>>(out);
}

// round 14
// speedup vs baseline: 1.0958x; 1.0958x over previous
#include <cuda_runtime.h>
#include <cstdint>

// Scratch for the three bilinear outputs (with the appended ones column):
// g_o[m][b*64 + k], k in [0,63); column 63 == 1.0f.  3*512*64*4 = 384 KB.
__device__ __align__(16) float g_o[3][512 * 64];

// ---------- packed f32x2 helpers (Blackwell) ----------
__device__ __forceinline__ unsigned long long pk(float lo, float hi) {
    unsigned long long r;
    asm("mov.b64 %0, {%1, %2};" : "=l"(r) : "f"(lo), "f"(hi));
    return r;
}
__device__ __forceinline__ unsigned long long f2(unsigned long long a,
                                                 unsigned long long b,
                                                 unsigned long long c) {
    unsigned long long d;
    asm("fma.rn.f32x2 %0, %1, %2, %3;" : "=l"(d) : "l"(a), "l"(b), "l"(c));
    return d;
}
__device__ __forceinline__ void upk(unsigned long long v, float& lo, float& hi) {
    asm("mov.b64 {%0, %1}, %2;" : "=f"(lo), "=f"(hi) : "l"(v));
}

// ---------------------------------------------------------------------------
// Stage 1: o_m[b,k] = sum_ij A[b,i] * W[k,i,j] * C[b,j] + bias[k]
// grid = (63 k, 3 forms, 4 b-tiles of 128), block = 256 threads:
//   2 threads per b, each owning one j-half (32 j's -> c2 = 16 f32x2 regs).
// W[k] staged in smem with rows padded to 80 floats, half1 at +48, so the two
// jh broadcast groups hit disjoint bank quads (single-phase LDS.128).
// A-rows staged in padded smem (stride 65) -> conflict-free scalar LDS.
// Pair-reduce with shfl.xor(1).
// ---------------------------------------------------------------------------
__global__ __launch_bounds__(256) void bilinear_k(
    const float* __restrict__ x, const float* __restrict__ y,
    const float* __restrict__ z,
    const float* __restrict__ W1, const float* __restrict__ b1,
    const float* __restrict__ W2, const float* __restrict__ b2,
    const float* __restrict__ W3, const float* __restrict__ b3) {
    __shared__ __align__(16) float Ws[64 * 80];   // row i at i*80; half1 at +48
    __shared__ float As[128 * 65];                // padded A rows

    const int k  = blockIdx.x;
    const int m  = blockIdx.y;
    const int bl = threadIdx.x >> 1;              // local b: 0..127
    const int jh = threadIdx.x & 1;               // j half
    const int b  = blockIdx.z * 128 + bl;

    const float* A;
    const float* C;
    const float* W;
    const float* bias;
    if (m == 0)      { A = x; C = y; W = W1; bias = b1; }
    else if (m == 1) { A = x; C = z; W = W2; bias = b2; }
    else             { A = y; C = z; W = W3; bias = b3; }

    // Stage W[k] into bank-padded smem. float4-wide, coalesced from GMEM.
    {
        const float4* Wg = (const float4*)(W + (size_t)k * 4096);
        #pragma unroll
        for (int q = 0; q < 4; ++q) {
            int idx4 = threadIdx.x + 256 * q;     // float4 index 0..1023
            float4 v = Wg[idx4];
            int i  = idx4 >> 4;                   // row
            int j4 = idx4 & 15;                   // float4 within row
            int off = (j4 < 8) ? (j4 * 4) : (48 + (j4 - 8) * 4);
            *(float4*)(Ws + i * 80 + off) = v;
        }
    }
    // Stage A-rows (coalesced read, padded write).
    {
        const float* Ag = A + (size_t)blockIdx.z * 128 * 64;
        #pragma unroll
        for (int q = 0; q < 32; ++q) {
            int idx = threadIdx.x + 256 * q;      // 0..8191
            As[(idx >> 6) * 65 + (idx & 63)] = Ag[idx];
        }
    }

    // Pack this thread's 32-wide C half into 16 f32x2 registers.
    unsigned long long c2[16];
    {
        const float4* c4 = (const float4*)(C + (size_t)b * 64 + jh * 32);
        #pragma unroll
        for (int q = 0; q < 8; ++q) {
            float4 v = c4[q];
            c2[2 * q]     = pk(v.x, v.y);
            c2[2 * q + 1] = pk(v.z, v.w);
        }
    }
    __syncthreads();

    unsigned long long accA = 0ull, accB = 0ull;
    const float* arow = As + bl * 65;
    const int jhoff = jh * 48;

    #pragma unroll 4
    for (int i = 0; i < 64; ++i) {
        const ulonglong2* wr = (const ulonglong2*)(Ws + i * 80 + jhoff);
        unsigned long long sA = 0ull, sB = 0ull;  // 2 chains for ILP
        #pragma unroll
        for (int q = 0; q < 8; ++q) {
            ulonglong2 w = wr[q];
            sA = f2(w.x, c2[2 * q],     sA);
            sB = f2(w.y, c2[2 * q + 1], sB);
        }
        float ai = arow[i];
        unsigned long long a2 = pk(ai, ai);
        accA = f2(a2, sA, accA);
        accB = f2(a2, sB, accB);
    }

    float la, ha, lb, hb;
    upk(accA, la, ha);
    upk(accB, lb, hb);
    float part = (la + ha) + (lb + hb);
    part += __shfl_xor_sync(0xffffffffu, part, 1);  // join the two j-halves

    if (jh == 0) {
        g_o[m][b * 64 + k] = part + __ldg(bias + k);
        if (k == 0) g_o[m][b * 64 + 63] = 1.0f;     // appended ones column
    }
}

// ---------------------------------------------------------------------------
// Stage 2: out[b, i*4096 + j*64 + k] = o1[b,i] * o2[b,j] * o3[b,k]
// grid = (64 i, 512 b), block = 256. Each thread's kq = tid&15 is fixed, so
// its o3 float4 lives in registers; 4 perfectly coalesced STG.128 per thread.
// Pure store-bandwidth kernel (~512 MB total) — 80% DRAM SOL already.
// ---------------------------------------------------------------------------
__global__ __launch_bounds__(256) void outer_k(float* __restrict__ out) {
    const int i = blockIdx.x;
    const int b = blockIdx.y;
    const float* o1 = g_o[0] + b * 64;
    const float* o2 = g_o[1] + b * 64;
    const float* o3 = g_o[2] + b * 64;

    const float o1i = __ldg(o1 + i);
    const float4 w = ((const float4*)o3)[threadIdx.x & 15];

    float4* out4 = (float4*)out + (size_t)b * 65536 + (size_t)i * 1024;
    const int jb = threadIdx.x >> 4;

    #pragma unroll
    for (int u = 0; u < 4; ++u) {
        float v = o1i * __ldg(o2 + jb + 16 * u);
        float4 r;
        r.x = v * w.x;
        r.y = v * w.y;
        r.z = v * w.z;
        r.w = v * w.w;
        out4[threadIdx.x + 256 * u] = r;
    }
}

extern "C" void kernel_launch(void* const* d_in, const int* in_sizes, int n_in,
                              void* d_out, int out_size) {
    const float* x  = (const float*)d_in[0];
    const float* y  = (const float*)d_in[1];
    const float* z  = (const float*)d_in[2];
    const float* W1 = (const float*)d_in[3];
    const float* b1 = (const float*)d_in[4];
    const float* W2 = (const float*)d_in[5];
    const float* b2 = (const float*)d_in[6];
    const float* W3 = (const float*)d_in[7];
    const float* b3 = (const float*)d_in[8];
    float* out = (float*)d_out;

    dim3 g1(63, 3, 4);
    bilinear_k<<<g1, 256>>>(x, y, z, W1, b1, W2, b2, W3, b3);

    dim3 g2(64, 512);
    outer_k<<<g2, 256>>>(out);
}